// round 14
// baseline (speedup 1.0000x reference)
#include <cuda_runtime.h>
#include <cuda_bf16.h>

// out[t, :] = W[x[t], :] + b    t in [0, 8192), D = 2048
//
// R13 -> R14: single change, __stcs -> __stwt on output stores.
// .wt does NOT allocate in L2: the 64MB output stream stops thrashing L2,
// the ~62MB of touched W rows stays L2-resident across graph replays
// (reads become L2 hits), and DRAM sees a pure full-line write stream —
// no read/write turnaround. Everything else is the proven best config:
// persistent depth-1 pipelined gather, GRID=1184 (8 CTAs/SM exactly
// resident), 2-ahead index prefetch, branch-light main loop.

#define D_MODEL 2048
#define D4      (D_MODEL / 4)   // 512 float4 per row
#define TOKENS  8192
#define GRID    1184            // 8 CTAs/SM * 148 SMs, all resident
#define NTHR    256
#define FULL_ITERS 6            // t = bid + k*GRID valid for all bids when k<=5

__global__ __launch_bounds__(NTHR, 8)
void embed_gather_pipe(const int* __restrict__ x,
                       const float4* __restrict__ W4,
                       const float4* __restrict__ b4,
                       float4* __restrict__ out4) {
    const int c0 = threadIdx.x;
    const int c1 = threadIdx.x + NTHR;

    const float4 bb0 = b4[c0];
    const float4 bb1 = b4[c1];

    int t = blockIdx.x;

    // prologue: current row loads + next index (bid + GRID <= 2367 < 8192)
    unsigned o = (unsigned)__ldg(x + t) * D4;
    unsigned r_nxt = (unsigned)__ldg(x + t + GRID);

    float4 a0 = W4[o + c0];
    float4 a1 = W4[o + c1];

#pragma unroll
    for (int it = 0; it < FULL_ITERS; it++) {
        const int t2 = t + 2 * GRID;
        unsigned r_nxt2 = 0;
        if (t2 < TOKENS) r_nxt2 = (unsigned)__ldg(x + t2);

        // issue next row's loads before consuming current
        const unsigned no = r_nxt * D4;
        float4 n0 = W4[no + c0];
        float4 n1 = W4[no + c1];

        float4 v0 = a0, v1 = a1;
        v0.x += bb0.x; v0.y += bb0.y; v0.z += bb0.z; v0.w += bb0.w;
        v1.x += bb1.x; v1.y += bb1.y; v1.z += bb1.z; v1.w += bb1.w;

        float4* __restrict__ dst = out4 + (unsigned)t * D4;
        __stwt(dst + c0, v0);       // write-through: no L2 allocation
        __stwt(dst + c1, v1);

        t += GRID;
        r_nxt = r_nxt2;
        a0 = n0; a1 = n1;
    }

    // tail: token t = bid + 6*GRID exists iff bid < 1088
    if (t < TOKENS) {
        float4 v0 = a0, v1 = a1;
        v0.x += bb0.x; v0.y += bb0.y; v0.z += bb0.z; v0.w += bb0.w;
        v1.x += bb1.x; v1.y += bb1.y; v1.z += bb1.z; v1.w += bb1.w;
        float4* __restrict__ dst = out4 + (unsigned)t * D4;
        __stwt(dst + c0, v0);
        __stwt(dst + c1, v1);
    }
}

extern "C" void kernel_launch(void* const* d_in, const int* in_sizes, int n_in,
                              void* d_out, int out_size) {
    const int*    x = (const int*)d_in[0];        // [4, 2048] int32
    const float4* W = (const float4*)d_in[1];     // [50257, 2048] f32
    const float4* b = (const float4*)d_in[2];     // [2048] f32
    float4* out = (float4*)d_out;                 // [4, 2048, 2048] f32

    embed_gather_pipe<<<GRID, NTHR>>>(x, W, b, out);
}

// round 15
// speedup vs baseline: 1.2010x; 1.2010x over previous
#include <cuda_runtime.h>
#include <cuda_bf16.h>

// out[t, :] = W[x[t], :] + b    t in [0, 8192), D = 2048
//
// FINAL: persistent depth-1 software-pipelined gather (best measured: 18.53us).
// Empirical roof for this pattern is ~18.5-19.3us: 128 MB compulsory L2
// traffic (64 MB random row reads + 64 MB output writes) with exposed
// long-scoreboard latency. Verified-neutral levers: TMA bulk loads/stores,
// MLP 2->8, cache policies (.cs/.wt/.ldcs), deeper pipelines (lose occupancy),
// index/ALU micro-trims. This config: GRID = 1184 = 8 CTAs/SM x 148 SMs
// (exactly resident, occ ~93%), next token's row loads issue while current
// token is consumed, indices prefetched two iterations ahead, evict-first
// output stores.

#define D_MODEL 2048
#define D4      (D_MODEL / 4)   // 512 float4 per row
#define TOKENS  8192
#define GRID    1184            // 8 CTAs/SM * 148 SMs
#define NTHR    256

__global__ __launch_bounds__(NTHR, 8)
void embed_gather_pipe(const int* __restrict__ x,
                       const float4* __restrict__ W4,
                       const float4* __restrict__ b4,
                       float4* __restrict__ out4) {
    const int c0 = threadIdx.x;
    const int c1 = threadIdx.x + NTHR;

    const float4 bb0 = b4[c0];
    const float4 bb1 = b4[c1];

    int t = blockIdx.x;                      // GRID < TOKENS, always valid
    int t1 = t + GRID;

    // prologue: current row loads + next index
    long long r_cur = (long long)__ldg(x + t);
    long long r_nxt = (t1 < TOKENS) ? (long long)__ldg(x + t1) : 0;

    float4 a0 = W4[r_cur * D4 + c0];
    float4 a1 = W4[r_cur * D4 + c1];

    for (;;) {
        const bool have_next = (t1 < TOKENS);

        // prefetch index two ahead (hides idx->row dependency)
        const int t2 = t1 + GRID;
        const long long r_nxt2 = (t2 < TOKENS) ? (long long)__ldg(x + t2) : 0;

        // issue next row's loads BEFORE consuming current (independent of stores)
        float4 n0, n1;
        if (have_next) {
            n0 = W4[r_nxt * D4 + c0];
            n1 = W4[r_nxt * D4 + c1];
        }

        // consume current token
        float4 v0 = a0, v1 = a1;
        v0.x += bb0.x; v0.y += bb0.y; v0.z += bb0.z; v0.w += bb0.w;
        v1.x += bb1.x; v1.y += bb1.y; v1.z += bb1.z; v1.w += bb1.w;

        float4* __restrict__ dst = out4 + (long long)t * D4;
        __stcs(dst + c0, v0);
        __stcs(dst + c1, v1);

        if (!have_next) break;
        t = t1; t1 = t2;
        r_nxt = r_nxt2;
        a0 = n0; a1 = n1;
    }
}

extern "C" void kernel_launch(void* const* d_in, const int* in_sizes, int n_in,
                              void* d_out, int out_size) {
    const int*    x = (const int*)d_in[0];        // [4, 2048] int32
    const float4* W = (const float4*)d_in[1];     // [50257, 2048] f32
    const float4* b = (const float4*)d_in[2];     // [2048] f32
    float4* out = (float4*)d_out;                 // [4, 2048, 2048] f32

    embed_gather_pipe<<<GRID, NTHR>>>(x, W, b, out);
}